// round 2
// baseline (speedup 1.0000x reference)
#include <cuda_runtime.h>

#define BB 32
#define NN 16384
#define PP 4096
#define CC 14

// scratch (no device allocation allowed)
__device__ double g_acc;
__device__ float g_cent[BB][CC][3];

__global__ void k_init() {
    g_acc = 0.0;
}

// One block per batch: class-mean centroids + chamfer + separation (tiny tail).
__global__ void k_centroids(const float* __restrict__ origin,
                            const int* __restrict__ target,
                            const float* __restrict__ cpred) {
    const int b = blockIdx.x;
    const int tid = threadIdx.x;

    __shared__ float s[CC][4];   // sum x, y, z, count
    __shared__ float cg[CC][3];  // finalized centroids

    if (tid < CC * 4) ((float*)s)[tid] = 0.0f;
    __syncthreads();

    const float* __restrict__ ox = origin + (size_t)b * 9 * PP;           // row 0 = x
    const float* __restrict__ oy = ox + PP;                                // row 1 = y
    const float* __restrict__ oz = ox + 2 * PP;                            // row 2 = z
    const int* __restrict__ tg = target + (size_t)b * PP;

    for (int p = tid; p < PP; p += blockDim.x) {
        int c = tg[p];
        c = min(max(c, 0), CC - 1);   // defensive clamp: never corrupt smem
        float x = ox[p], y = oy[p], z = oz[p];
        atomicAdd(&s[c][0], x);
        atomicAdd(&s[c][1], y);
        atomicAdd(&s[c][2], z);
        atomicAdd(&s[c][3], 1.0f);
    }
    __syncthreads();

    if (tid < CC) {
        float cnt = fmaxf(s[tid][3], 1.0f);
        float x = s[tid][0] / cnt;
        float y = s[tid][1] / cnt;
        float z = s[tid][2] / cnt;
        cg[tid][0] = x; cg[tid][1] = y; cg[tid][2] = z;
        g_cent[b][tid][0] = x;
        g_cent[b][tid][1] = y;
        g_cent[b][tid][2] = z;
    }
    __syncthreads();

    if (tid == 0) {
        // centroids_pred: [B, 3, C] -> pred[i] = (cp[0*C+i], cp[1*C+i], cp[2*C+i])
        const float* __restrict__ cp = cpred + (size_t)b * 3 * CC;
        float Dm[CC][CC];
        #pragma unroll
        for (int i = 0; i < CC; i++) {
            float px = cp[i], py = cp[CC + i], pz = cp[2 * CC + i];
            #pragma unroll
            for (int j = 0; j < CC; j++) {
                float dx = px - cg[j][0];
                float dy = py - cg[j][1];
                float dz = pz - cg[j][2];
                Dm[i][j] = dx * dx + dy * dy + dz * dz;
            }
        }
        // l1: sum_j min_i D[i][j]
        float l1 = 0.0f;
        #pragma unroll
        for (int j = 0; j < CC; j++) {
            float m = Dm[0][j];
            #pragma unroll
            for (int i = 1; i < CC; i++) m = fminf(m, Dm[i][j]);
            l1 += m;
        }
        // l2: sum_i min_j D[i][j]; separation: smallest/2nd-smallest of sqrt(D) per row i
        float l2 = 0.0f, sep = 0.0f;
        #pragma unroll
        for (int i = 0; i < CC; i++) {
            float mm = 3.402823e38f;
            float m1 = 3.402823e38f, m2 = 3.402823e38f;
            #pragma unroll
            for (int j = 0; j < CC; j++) {
                float d = Dm[i][j];
                mm = fminf(mm, d);
                float dd = sqrtf(d);
                if (dd < m1) { m2 = m1; m1 = dd; }
                else if (dd < m2) { m2 = dd; }
            }
            l2 += mm;
            sep += m1 / m2;
        }
        atomicAdd(&g_acc, (double)(l1 + l2 + 0.1f * sep));
    }
}

__device__ __forceinline__ float smooth_l1(float x) {
    float ax = fabsf(x);
    return (ax < 1.0f) ? (0.5f * x * x) : (ax - 0.5f);
}

// Main streaming kernel: min-centroid distance + smooth-L1 over B*N points.
// grid = (NN / (256*4), BB), block = 256, 4 points per thread (float4 loads).
__global__ void __launch_bounds__(256) k_dist(const float* __restrict__ disp,
                                              const float* __restrict__ sub) {
    const int b = blockIdx.y;
    __shared__ float cgx[CC], cgy[CC], cgz[CC];
    if (threadIdx.x < CC) {
        cgx[threadIdx.x] = g_cent[b][threadIdx.x][0];
        cgy[threadIdx.x] = g_cent[b][threadIdx.x][1];
        cgz[threadIdx.x] = g_cent[b][threadIdx.x][2];
    }
    __syncthreads();

    const int n0 = (blockIdx.x * blockDim.x + threadIdx.x) * 4;

    const float4 d4 = *(const float4*)(disp + (size_t)b * NN + n0);
    const float* __restrict__ sb = sub + (size_t)b * 3 * NN;
    const float4 x4 = *(const float4*)(sb + n0);
    const float4 y4 = *(const float4*)(sb + NN + n0);
    const float4 z4 = *(const float4*)(sb + 2 * NN + n0);

    float xs[4] = {x4.x, x4.y, x4.z, x4.w};
    float ys[4] = {y4.x, y4.y, y4.z, y4.w};
    float zs[4] = {z4.x, z4.y, z4.z, z4.w};
    float ds[4] = {d4.x, d4.y, d4.z, d4.w};

    float local = 0.0f;
    #pragma unroll
    for (int k = 0; k < 4; k++) {
        float mind2 = 3.402823e38f;
        #pragma unroll
        for (int c = 0; c < CC; c++) {
            float dx = xs[k] - cgx[c];
            float dy = ys[k] - cgy[c];
            float dz = zs[k] - cgz[c];
            float d2 = fmaf(dx, dx, fmaf(dy, dy, dz * dz));
            mind2 = fminf(mind2, d2);
        }
        local += smooth_l1(ds[k] - sqrtf(mind2));
    }

    // block reduction: warp shuffle, then shared, then one double atomic
    #pragma unroll
    for (int off = 16; off > 0; off >>= 1)
        local += __shfl_xor_sync(0xFFFFFFFFu, local, off);

    __shared__ float warp_sums[8];
    const int lane = threadIdx.x & 31;
    const int wid = threadIdx.x >> 5;
    if (lane == 0) warp_sums[wid] = local;
    __syncthreads();
    if (wid == 0) {
        float v = (lane < 8) ? warp_sums[lane] : 0.0f;
        #pragma unroll
        for (int off = 4; off > 0; off >>= 1)
            v += __shfl_xor_sync(0xFFFFFFFFu, v, off);
        if (lane == 0) atomicAdd(&g_acc, (double)v);
    }
}

__global__ void k_finalize(float* __restrict__ out) {
    out[0] = (float)g_acc;
}

extern "C" void kernel_launch(void* const* d_in, const int* in_sizes, int n_in,
                              void* d_out, int out_size) {
    const float* disp   = (const float*)d_in[0];       // [B, N]
    const float* sub    = (const float*)d_in[1];       // [B, 3, N]
    const float* cpred  = (const float*)d_in[2];       // [B, 3, C]
    const float* origin = (const float*)d_in[3];       // [B, 9, P]
    const int*   tg     = (const int*)d_in[4];         // [B, P] (int64 in ref, canonicalized to int32)
    float* out = (float*)d_out;

    k_init<<<1, 1>>>();
    k_centroids<<<BB, 256>>>(origin, tg, cpred);
    dim3 grid(NN / (256 * 4), BB);
    k_dist<<<grid, 256>>>(disp, sub);
    k_finalize<<<1, 1>>>(out);
}

// round 3
// speedup vs baseline: 1.7752x; 1.7752x over previous
#include <cuda_runtime.h>

#define BB 32
#define NN 16384
#define PP 4096
#define CC 14
#define DIST_BLOCKS (16 * 32)

__device__ double g_acc;                 // zero-initialized at module load; reset by last dist block
__device__ unsigned g_count;             // arrival counter, self-resetting
__device__ float g_cent[BB][CC][3];

// ---------------------------------------------------------------------------
// Kernel 1: per-batch class-mean centroids (register-privatized, NO atomics)
// + parallel 14x14 chamfer/separation tail. One block per batch, 512 threads.
// ---------------------------------------------------------------------------
__global__ void __launch_bounds__(512) k_centroids(const float* __restrict__ origin,
                                                   const int* __restrict__ target,
                                                   const float* __restrict__ cpred) {
    const int b = blockIdx.x;
    const int tid = threadIdx.x;
    const int lane = tid & 31;
    const int wid = tid >> 5;

    const float* __restrict__ ox = origin + (size_t)b * 9 * PP;
    const float* __restrict__ oy = ox + PP;
    const float* __restrict__ oz = ox + 2 * PP;
    const int* __restrict__ tg = target + (size_t)b * PP;

    // per-thread register bins: [class][x,y,z,count]
    float bins[CC * 4];
    #pragma unroll
    for (int k = 0; k < CC * 4; k++) bins[k] = 0.0f;

    #pragma unroll
    for (int i = 0; i < PP / 512; i++) {
        const int p = tid + i * 512;
        const int c = tg[p];
        const float x = ox[p], y = oy[p], z = oz[p];
        #pragma unroll
        for (int cc = 0; cc < CC; cc++) {
            if (c == cc) {                 // -> predicated FADDs, no atomics
                bins[cc * 4 + 0] += x;
                bins[cc * 4 + 1] += y;
                bins[cc * 4 + 2] += z;
                bins[cc * 4 + 3] += 1.0f;
            }
        }
    }

    // warp reduction of all 56 accumulators
    #pragma unroll
    for (int k = 0; k < CC * 4; k++) {
        #pragma unroll
        for (int off = 16; off > 0; off >>= 1)
            bins[k] += __shfl_xor_sync(0xFFFFFFFFu, bins[k], off);
    }

    // cross-warp reduction through shared memory
    __shared__ float red[16][CC * 4];
    __shared__ float fin[CC * 4];
    __shared__ float cgx[CC], cgy[CC], cgz[CC];
    if (lane == 0) {
        #pragma unroll
        for (int k = 0; k < CC * 4; k++) red[wid][k] = bins[k];
    }
    __syncthreads();
    if (tid < CC * 4) {
        float s = 0.0f;
        #pragma unroll
        for (int w = 0; w < 16; w++) s += red[w][tid];
        fin[tid] = s;
    }
    __syncthreads();
    if (tid < CC) {
        const float cnt = fmaxf(fin[tid * 4 + 3], 1.0f);
        const float x = fin[tid * 4 + 0] / cnt;
        const float y = fin[tid * 4 + 1] / cnt;
        const float z = fin[tid * 4 + 2] / cnt;
        cgx[tid] = x; cgy[tid] = y; cgz[tid] = z;
        g_cent[b][tid][0] = x;
        g_cent[b][tid][1] = y;
        g_cent[b][tid][2] = z;
    }
    __syncthreads();

    // chamfer + separation: thread t (t<14) owns pred-centroid row t AND gt-centroid column t
    if (tid < 32) {
        float local = 0.0f;
        if (tid < CC) {
            const float* __restrict__ cp = cpred + (size_t)b * 3 * CC;
            const float px = cp[tid], py = cp[CC + tid], pz = cp[2 * CC + tid];

            // row t: min over gt-centroids j (l2 term) + two smallest sqrt-dists (separation)
            float rmin = 3.402823e38f, m1 = 3.402823e38f, m2 = 3.402823e38f;
            #pragma unroll
            for (int j = 0; j < CC; j++) {
                const float dx = px - cgx[j], dy = py - cgy[j], dz = pz - cgz[j];
                const float d2 = fmaf(dx, dx, fmaf(dy, dy, dz * dz));
                rmin = fminf(rmin, d2);
                const float dd = sqrtf(d2);
                if (dd < m1) { m2 = m1; m1 = dd; }
                else if (dd < m2) { m2 = dd; }
            }
            // column t: min over pred-centroids i (l1 term)
            const float gx = cgx[tid], gy = cgy[tid], gz = cgz[tid];
            float cmin = 3.402823e38f;
            #pragma unroll
            for (int i = 0; i < CC; i++) {
                const float dx = cp[i] - gx, dy = cp[CC + i] - gy, dz = cp[2 * CC + i] - gz;
                cmin = fminf(cmin, fmaf(dx, dx, fmaf(dy, dy, dz * dz)));
            }
            local = rmin + cmin + 0.1f * (m1 / m2);
        }
        #pragma unroll
        for (int off = 16; off > 0; off >>= 1)
            local += __shfl_xor_sync(0xFFFFFFFFu, local, off);
        if (tid == 0) atomicAdd(&g_acc, (double)local);
    }
}

// ---------------------------------------------------------------------------
// Kernel 2: distance-estimate loss (streaming, float4) + fused finalize via
// last-block arrival counter. grid (16, 32), 256 threads, 4 pts/thread.
// ---------------------------------------------------------------------------
__device__ __forceinline__ float smooth_l1(float x) {
    const float ax = fabsf(x);
    return (ax < 1.0f) ? (0.5f * x * x) : (ax - 0.5f);
}

__global__ void __launch_bounds__(256) k_dist(const float* __restrict__ disp,
                                              const float* __restrict__ sub,
                                              float* __restrict__ out) {
    const int b = blockIdx.y;
    __shared__ float cgx[CC], cgy[CC], cgz[CC];
    if (threadIdx.x < CC) {
        cgx[threadIdx.x] = g_cent[b][threadIdx.x][0];
        cgy[threadIdx.x] = g_cent[b][threadIdx.x][1];
        cgz[threadIdx.x] = g_cent[b][threadIdx.x][2];
    }
    __syncthreads();

    const int n0 = (blockIdx.x * blockDim.x + threadIdx.x) * 4;

    const float4 d4 = *(const float4*)(disp + (size_t)b * NN + n0);
    const float* __restrict__ sb = sub + (size_t)b * 3 * NN;
    const float4 x4 = *(const float4*)(sb + n0);
    const float4 y4 = *(const float4*)(sb + NN + n0);
    const float4 z4 = *(const float4*)(sb + 2 * NN + n0);

    const float xs[4] = {x4.x, x4.y, x4.z, x4.w};
    const float ys[4] = {y4.x, y4.y, y4.z, y4.w};
    const float zs[4] = {z4.x, z4.y, z4.z, z4.w};
    const float ds[4] = {d4.x, d4.y, d4.z, d4.w};

    float local = 0.0f;
    #pragma unroll
    for (int k = 0; k < 4; k++) {
        float mind2 = 3.402823e38f;
        #pragma unroll
        for (int c = 0; c < CC; c++) {
            const float dx = xs[k] - cgx[c];
            const float dy = ys[k] - cgy[c];
            const float dz = zs[k] - cgz[c];
            mind2 = fminf(mind2, fmaf(dx, dx, fmaf(dy, dy, dz * dz)));
        }
        local += smooth_l1(ds[k] - sqrtf(mind2));
    }

    #pragma unroll
    for (int off = 16; off > 0; off >>= 1)
        local += __shfl_xor_sync(0xFFFFFFFFu, local, off);

    __shared__ float warp_sums[8];
    const int lane = threadIdx.x & 31;
    const int wid = threadIdx.x >> 5;
    if (lane == 0) warp_sums[wid] = local;
    __syncthreads();

    if (threadIdx.x == 0) {
        float v = 0.0f;
        #pragma unroll
        for (int w = 0; w < 8; w++) v += warp_sums[w];
        atomicAdd(&g_acc, (double)v);
        __threadfence();
        const unsigned t = atomicAdd(&g_count, 1u);
        if (t == DIST_BLOCKS - 1) {
            const double tot = atomicAdd(&g_acc, 0.0);   // safe read after all fenced adds
            out[0] = (float)tot;
            g_acc = 0.0;      // reset for next replay (deterministic)
            g_count = 0;
        }
    }
}

extern "C" void kernel_launch(void* const* d_in, const int* in_sizes, int n_in,
                              void* d_out, int out_size) {
    const float* disp   = (const float*)d_in[0];       // [B, N]
    const float* sub    = (const float*)d_in[1];       // [B, 3, N]
    const float* cpred  = (const float*)d_in[2];       // [B, 3, C]
    const float* origin = (const float*)d_in[3];       // [B, 9, P]
    const int*   tg     = (const int*)d_in[4];         // [B, P]
    float* out = (float*)d_out;

    k_centroids<<<BB, 512>>>(origin, tg, cpred);
    dim3 grid(16, BB);
    k_dist<<<grid, 256>>>(disp, sub, out);
}

// round 4
// speedup vs baseline: 2.1418x; 1.2065x over previous
#include <cuda_runtime.h>

#define BB 32
#define NN 16384
#define PP 4096
#define CC 14
#define TPB 256
#define PTS 8
#define SEGS (NN / (TPB * PTS))          // 8 dist segments per batch
#define NBLK (BB * SEGS)                 // 256 total blocks
#define CBB  4                           // centroid blocks per batch
#define NCB  (BB * CBB)                  // 128 centroid blocks (< 148, all wave-1)
#define CPTS (PP / (CBB * TPB))          // 4 centroid points per thread

__device__ double g_acc;                 // zero at module load; reset each replay
__device__ unsigned g_count;
__device__ unsigned g_bcnt[BB];
__device__ float g_sums[BB][CC * 4];
__device__ float g_cent[BB][CC][3];
__device__ volatile int g_flag[BB];

__device__ __forceinline__ float smooth_l1(float x) {
    const float ax = fabsf(x);
    return (ax < 1.0f) ? (0.5f * x * x) : (ax - 0.5f);
}

__global__ void __launch_bounds__(TPB) k_fused(
        const float* __restrict__ disp, const float* __restrict__ sub,
        const float* __restrict__ cpred, const float* __restrict__ origin,
        const int* __restrict__ tgt, float* __restrict__ out)
{
    const int bid = blockIdx.x;
    const int tid = threadIdx.x;
    const int lane = tid & 31, wid = tid >> 5;

    __shared__ float red[TPB / 32][CC * 4];
    __shared__ float s_cg[3][CC];
    __shared__ int s_last;

    // ================= phase 1: centroids (blocks 0..NCB-1) =================
    if (bid < NCB) {
        const int b = bid / CBB;
        const int q = bid % CBB;
        const int base = q * (PP / CBB);
        const float* __restrict__ ox = origin + (size_t)b * 9 * PP + base;
        const float* __restrict__ oy = ox + PP;
        const float* __restrict__ oz = ox + 2 * PP;
        const int* __restrict__ tg = tgt + (size_t)b * PP + base;

        float bins[CC * 4];
        #pragma unroll
        for (int k = 0; k < CC * 4; k++) bins[k] = 0.0f;

        #pragma unroll
        for (int i = 0; i < CPTS; i++) {
            const int p = tid + i * TPB;
            const int c = tg[p];
            const float x = ox[p], y = oy[p], z = oz[p];
            #pragma unroll
            for (int cc = 0; cc < CC; cc++) {
                if (c == cc) {             // predicated FADDs, no atomics
                    bins[cc * 4 + 0] += x;
                    bins[cc * 4 + 1] += y;
                    bins[cc * 4 + 2] += z;
                    bins[cc * 4 + 3] += 1.0f;
                }
            }
        }
        #pragma unroll
        for (int k = 0; k < CC * 4; k++) {
            #pragma unroll
            for (int off = 16; off > 0; off >>= 1)
                bins[k] += __shfl_xor_sync(0xFFFFFFFFu, bins[k], off);
        }
        if (lane == 0) {
            #pragma unroll
            for (int k = 0; k < CC * 4; k++) red[wid][k] = bins[k];
        }
        __syncthreads();
        if (tid < CC * 4) {
            float s = 0.0f;
            #pragma unroll
            for (int w = 0; w < TPB / 32; w++) s += red[w][tid];
            atomicAdd(&g_sums[b][tid], s);
        }
        __threadfence();
        __syncthreads();
        if (tid == 0)
            s_last = (atomicAdd(&g_bcnt[b], 1u) == CBB - 1);
        __syncthreads();

        if (s_last) {
            // last of 4 blocks for this batch: finalize means + chamfer tail
            if (tid < CC) {
                const float sx = g_sums[b][tid * 4 + 0];
                const float sy = g_sums[b][tid * 4 + 1];
                const float sz = g_sums[b][tid * 4 + 2];
                const float cw = g_sums[b][tid * 4 + 3];
                g_sums[b][tid * 4 + 0] = 0.0f;   // reset for next replay
                g_sums[b][tid * 4 + 1] = 0.0f;
                g_sums[b][tid * 4 + 2] = 0.0f;
                g_sums[b][tid * 4 + 3] = 0.0f;
                const float inv = 1.0f / fmaxf(cw, 1.0f);
                const float x = sx * inv, y = sy * inv, z = sz * inv;
                s_cg[0][tid] = x; s_cg[1][tid] = y; s_cg[2][tid] = z;
                g_cent[b][tid][0] = x;
                g_cent[b][tid][1] = y;
                g_cent[b][tid][2] = z;
                __threadfence();
            }
            __syncthreads();
            if (tid < 32) {
                float local = 0.0f;
                if (tid < CC) {
                    const float* __restrict__ cp = cpred + (size_t)b * 3 * CC;
                    const float px = cp[tid], py = cp[CC + tid], pz = cp[2 * CC + tid];
                    // row tid over gt centroids: l2 min + two smallest dists (separation)
                    float rmin = 3.402823e38f, m1 = 3.402823e38f, m2 = 3.402823e38f;
                    #pragma unroll
                    for (int j = 0; j < CC; j++) {
                        const float dx = px - s_cg[0][j], dy = py - s_cg[1][j], dz = pz - s_cg[2][j];
                        const float d2 = fmaf(dx, dx, fmaf(dy, dy, dz * dz));
                        rmin = fminf(rmin, d2);
                        const float dd = sqrtf(d2);
                        if (dd < m1) { m2 = m1; m1 = dd; }
                        else if (dd < m2) { m2 = dd; }
                    }
                    // column tid over pred centroids: l1 min
                    const float gx = s_cg[0][tid], gy = s_cg[1][tid], gz = s_cg[2][tid];
                    float cmin = 3.402823e38f;
                    #pragma unroll
                    for (int i = 0; i < CC; i++) {
                        const float dx = cp[i] - gx, dy = cp[CC + i] - gy, dz = cp[2 * CC + i] - gz;
                        cmin = fminf(cmin, fmaf(dx, dx, fmaf(dy, dy, dz * dz)));
                    }
                    local = rmin + cmin + 0.1f * (m1 / m2);
                }
                #pragma unroll
                for (int off = 16; off > 0; off >>= 1)
                    local += __shfl_xor_sync(0xFFFFFFFFu, local, off);
                if (tid == 0) {
                    atomicAdd(&g_acc, (double)local);
                    g_bcnt[b] = 0;           // reset for next replay
                    __threadfence();
                    g_flag[b] = 1;           // release dist blocks for batch b
                }
            }
        }
    }

    // ================= phase 2: distance loss (all blocks) =================
    const int db = bid / SEGS;
    const int seg = bid % SEGS;
    const float* __restrict__ dp = disp + (size_t)db * NN;
    const float* __restrict__ px = sub + (size_t)db * 3 * NN;
    const float* __restrict__ py = px + NN;
    const float* __restrict__ pz = px + 2 * NN;
    const int o0 = seg * (TPB * PTS) + tid * 4;
    const int o1 = o0 + TPB * 4;

    // issue all loads before the spin (independent of centroids)
    const float4 dA = *(const float4*)(dp + o0);
    const float4 dB = *(const float4*)(dp + o1);
    const float4 xA = *(const float4*)(px + o0);
    const float4 xB = *(const float4*)(px + o1);
    const float4 yA = *(const float4*)(py + o0);
    const float4 yB = *(const float4*)(py + o1);
    const float4 zA = *(const float4*)(pz + o0);
    const float4 zB = *(const float4*)(pz + o1);

    if (tid == 0) {
        while (g_flag[db] == 0) __nanosleep(64);
    }
    __syncthreads();

    __shared__ float c_x[CC], c_y[CC], c_z[CC];
    if (tid < CC) {
        c_x[tid] = g_cent[db][tid][0];
        c_y[tid] = g_cent[db][tid][1];
        c_z[tid] = g_cent[db][tid][2];
    }
    __syncthreads();

    const float xs[8] = {xA.x, xA.y, xA.z, xA.w, xB.x, xB.y, xB.z, xB.w};
    const float ys[8] = {yA.x, yA.y, yA.z, yA.w, yB.x, yB.y, yB.z, yB.w};
    const float zs[8] = {zA.x, zA.y, zA.z, zA.w, zB.x, zB.y, zB.z, zB.w};
    const float ds[8] = {dA.x, dA.y, dA.z, dA.w, dB.x, dB.y, dB.z, dB.w};

    float local = 0.0f;
    #pragma unroll
    for (int k = 0; k < 8; k++) {
        float ma = 3.402823e38f, mb = 3.402823e38f;   // dual chains for ILP
        #pragma unroll
        for (int c = 0; c < CC; c += 2) {
            {
                const float dx = xs[k] - c_x[c], dy = ys[k] - c_y[c], dz = zs[k] - c_z[c];
                ma = fminf(ma, fmaf(dx, dx, fmaf(dy, dy, dz * dz)));
            }
            {
                const float dx = xs[k] - c_x[c + 1], dy = ys[k] - c_y[c + 1], dz = zs[k] - c_z[c + 1];
                mb = fminf(mb, fmaf(dx, dx, fmaf(dy, dy, dz * dz)));
            }
        }
        local += smooth_l1(ds[k] - sqrtf(fminf(ma, mb)));
    }

    #pragma unroll
    for (int off = 16; off > 0; off >>= 1)
        local += __shfl_xor_sync(0xFFFFFFFFu, local, off);

    __shared__ float wsum[TPB / 32];
    if (lane == 0) wsum[wid] = local;
    __syncthreads();
    if (tid == 0) {
        float v = 0.0f;
        #pragma unroll
        for (int w = 0; w < TPB / 32; w++) v += wsum[w];
        atomicAdd(&g_acc, (double)v);
        __threadfence();
        if (atomicAdd(&g_count, 1u) == NBLK - 1) {
            const double tot = atomicAdd(&g_acc, 0.0);
            out[0] = (float)tot;
            g_acc = 0.0;                 // reset everything for next replay
            g_count = 0;
            #pragma unroll
            for (int i = 0; i < BB; i++) g_flag[i] = 0;
        }
    }
}

extern "C" void kernel_launch(void* const* d_in, const int* in_sizes, int n_in,
                              void* d_out, int out_size) {
    const float* disp   = (const float*)d_in[0];       // [B, N]
    const float* sub    = (const float*)d_in[1];       // [B, 3, N]
    const float* cpred  = (const float*)d_in[2];       // [B, 3, C]
    const float* origin = (const float*)d_in[3];       // [B, 9, P]
    const int*   tg     = (const int*)d_in[4];         // [B, P]
    float* out = (float*)d_out;

    k_fused<<<NBLK, TPB>>>(disp, sub, cpred, origin, tg, out);
}

// round 5
// speedup vs baseline: 2.3519x; 1.0981x over previous
#include <cuda_runtime.h>

#define BB 32
#define NN 16384
#define PP 4096
#define CC 14
#define TPB 256
#define PTS 8
#define SEGS (NN / (TPB * PTS))          // 8 dist segments per batch
#define NBLK (BB * SEGS)                 // 256 blocks total
#define CBB 4                            // centroid blocks per batch (seg 0..3)
#define CPTS (PP / (CBB * TPB))          // 4 centroid points per thread

// all zero-initialized at module load; every replay restores them
__device__ unsigned g_count;
__device__ unsigned g_bcnt[BB];
__device__ float    g_sums[BB][CC * 4];
__device__ float4   g_centP[BB][CC];     // (-2cx, -2cy, -2cz, ||c||^2)
__device__ unsigned g_flag[BB];
__device__ float    g_part[NBLK];

__device__ __forceinline__ float smooth_l1(float x) {
    const float ax = fabsf(x);
    return (ax < 1.0f) ? (0.5f * x * x) : (ax - 0.5f);
}
__device__ __forceinline__ float sqrt_fast(float x) {
    float r;
    asm("sqrt.approx.f32 %0, %1;" : "=f"(r) : "f"(x));
    return r;
}
__device__ __forceinline__ unsigned ld_acq(const unsigned* p) {
    unsigned v;
    asm volatile("ld.acquire.gpu.u32 %0, [%1];" : "=r"(v) : "l"(p) : "memory");
    return v;
}
__device__ __forceinline__ void st_rel(unsigned* p, unsigned v) {
    asm volatile("st.release.gpu.u32 [%0], %1;" :: "l"(p), "r"(v) : "memory");
}
__device__ __forceinline__ unsigned atom_inc_acqrel(unsigned* p) {
    unsigned old;
    asm volatile("atom.acq_rel.gpu.add.u32 %0, [%1], %2;"
                 : "=r"(old) : "l"(p), "r"(1u) : "memory");
    return old;
}

__global__ void __launch_bounds__(TPB) k_fused(
        const float* __restrict__ disp, const float* __restrict__ sub,
        const float* __restrict__ cpred, const float* __restrict__ origin,
        const int* __restrict__ tgt, float* __restrict__ out)
{
    const int bid = blockIdx.x;
    const int tid = threadIdx.x;
    const int lane = tid & 31, wid = tid >> 5;
    const int b = bid / SEGS;
    const int seg = bid % SEGS;

    __shared__ float red[TPB / 32][CC * 4];
    __shared__ float fin[CC * 4];
    __shared__ float s_cgx[CC], s_cgy[CC], s_cgz[CC];
    __shared__ float4 s_c[CC];
    __shared__ float wsum[TPB / 32];
    __shared__ double dsum[TPB / 32];
    __shared__ int s_lastc, s_win;

    float extra = 0.0f;   // chamfer+separation contribution (winner-leader tid0 only)

    // ================= phase 1: centroids (seg < 4) =================
    if (seg < CBB) {
        const float* __restrict__ ox = origin + (size_t)b * 9 * PP + seg * (PP / CBB);
        const float* __restrict__ oy = ox + PP;
        const float* __restrict__ oz = ox + 2 * PP;
        const int* __restrict__ tg = tgt + (size_t)b * PP + seg * (PP / CBB);

        // vectorized loads: 4 consecutive points per thread
        const int4 c4 = *(const int4*)(tg + tid * 4);
        const float4 x4 = *(const float4*)(ox + tid * 4);
        const float4 y4 = *(const float4*)(oy + tid * 4);
        const float4 z4 = *(const float4*)(oz + tid * 4);
        const int cs[4] = {c4.x, c4.y, c4.z, c4.w};
        const float px[4] = {x4.x, x4.y, x4.z, x4.w};
        const float py[4] = {y4.x, y4.y, y4.z, y4.w};
        const float pz[4] = {z4.x, z4.y, z4.z, z4.w};

        float bins[CC * 4];
        #pragma unroll
        for (int k = 0; k < CC * 4; k++) bins[k] = 0.0f;
        #pragma unroll
        for (int i = 0; i < CPTS; i++) {
            const int c = cs[i];
            #pragma unroll
            for (int cc = 0; cc < CC; cc++) {
                if (c == cc) {             // predicated FADDs
                    bins[cc * 4 + 0] += px[i];
                    bins[cc * 4 + 1] += py[i];
                    bins[cc * 4 + 2] += pz[i];
                    bins[cc * 4 + 3] += 1.0f;
                }
            }
        }
        #pragma unroll
        for (int k = 0; k < CC * 4; k++) {
            #pragma unroll
            for (int off = 16; off > 0; off >>= 1)
                bins[k] += __shfl_xor_sync(0xFFFFFFFFu, bins[k], off);
        }
        if (lane == 0) {
            #pragma unroll
            for (int k = 0; k < CC * 4; k++) red[wid][k] = bins[k];
        }
        __syncthreads();
        if (tid < CC * 4) {
            float s = 0.0f;
            #pragma unroll
            for (int w = 0; w < TPB / 32; w++) s += red[w][tid];
            atomicAdd(&g_sums[b][tid], s);   // relaxed; published by acq_rel below
        }
        __syncthreads();
        if (tid == 0)
            s_lastc = (atom_inc_acqrel(&g_bcnt[b]) == CBB - 1);
        __syncthreads();

        if (s_lastc) {
            if (tid < CC * 4) {
                fin[tid] = g_sums[b][tid];
                g_sums[b][tid] = 0.0f;       // reset for next replay
            }
            __syncthreads();
            if (tid < CC) {
                const float cnt = fmaxf(fin[tid * 4 + 3], 1.0f);
                const float x = fin[tid * 4 + 0] / cnt;
                const float y = fin[tid * 4 + 1] / cnt;
                const float z = fin[tid * 4 + 2] / cnt;
                s_cgx[tid] = x; s_cgy[tid] = y; s_cgz[tid] = z;
                g_centP[b][tid] = make_float4(-2.0f * x, -2.0f * y, -2.0f * z,
                                              fmaf(x, x, fmaf(y, y, z * z)));
            }
            __syncthreads();
            if (tid == 0) {
                g_bcnt[b] = 0;               // reset (ordered by release below)
                st_rel(&g_flag[b], 1u);      // release dist blocks ASAP
            }
            // chamfer + separation overlaps pollers' dist start
            if (tid < 32) {
                float local = 0.0f;
                if (tid < CC) {
                    const float* __restrict__ cp = cpred + (size_t)b * 3 * CC;
                    const float qx = cp[tid], qy = cp[CC + tid], qz = cp[2 * CC + tid];
                    float rmin = 3.4e38f, m1 = 3.4e38f, m2 = 3.4e38f;
                    #pragma unroll
                    for (int j = 0; j < CC; j++) {
                        const float dx = qx - s_cgx[j], dy = qy - s_cgy[j], dz = qz - s_cgz[j];
                        const float d2 = fmaf(dx, dx, fmaf(dy, dy, dz * dz));
                        rmin = fminf(rmin, d2);
                        const float dd = sqrt_fast(d2);
                        if (dd < m1) { m2 = m1; m1 = dd; }
                        else if (dd < m2) { m2 = dd; }
                    }
                    const float gx = s_cgx[tid], gy = s_cgy[tid], gz = s_cgz[tid];
                    float cmin = 3.4e38f;
                    #pragma unroll
                    for (int i = 0; i < CC; i++) {
                        const float dx = cp[i] - gx, dy = cp[CC + i] - gy, dz = cp[2 * CC + i] - gz;
                        cmin = fminf(cmin, fmaf(dx, dx, fmaf(dy, dy, dz * dz)));
                    }
                    local = rmin + cmin + 0.1f * (m1 / m2);
                }
                #pragma unroll
                for (int off = 16; off > 0; off >>= 1)
                    local += __shfl_xor_sync(0xFFFFFFFFu, local, off);
                if (tid == 0) extra = local;
            }
        }
    }

    // ================= phase 2: distance loss (all blocks) =================
    {
        const float* __restrict__ dp = disp + (size_t)b * NN;
        const float* __restrict__ sx = sub + (size_t)b * 3 * NN;
        const float* __restrict__ sy = sx + NN;
        const float* __restrict__ sz = sx + 2 * NN;
        const int o0 = seg * (TPB * PTS) + tid * 4;
        const int o1 = o0 + TPB * 4;

        // issue all loads + ||p||^2 BEFORE the spin (off critical path)
        const float4 dA = *(const float4*)(dp + o0);
        const float4 dB = *(const float4*)(dp + o1);
        const float4 xA = *(const float4*)(sx + o0);
        const float4 xB = *(const float4*)(sx + o1);
        const float4 yA = *(const float4*)(sy + o0);
        const float4 yB = *(const float4*)(sy + o1);
        const float4 zA = *(const float4*)(sz + o0);
        const float4 zB = *(const float4*)(sz + o1);

        const float xs[8] = {xA.x, xA.y, xA.z, xA.w, xB.x, xB.y, xB.z, xB.w};
        const float ys[8] = {yA.x, yA.y, yA.z, yA.w, yB.x, yB.y, yB.z, yB.w};
        const float zs[8] = {zA.x, zA.y, zA.z, zA.w, zB.x, zB.y, zB.z, zB.w};
        const float ds[8] = {dA.x, dA.y, dA.z, dA.w, dB.x, dB.y, dB.z, dB.w};
        float pn[8];
        #pragma unroll
        for (int k = 0; k < 8; k++)
            pn[k] = fmaf(xs[k], xs[k], fmaf(ys[k], ys[k], zs[k] * zs[k]));

        // acquire-poll + fetch packed centroids (lanes 0..13 of warp 0)
        if (tid < CC) {
            while (ld_acq(&g_flag[b]) == 0u) __nanosleep(32);
            s_c[tid] = g_centP[b][tid];
        }
        __syncthreads();

        float tmin[8];
        #pragma unroll
        for (int k = 0; k < 8; k++) tmin[k] = 3.4e38f;
        #pragma unroll
        for (int c = 0; c < CC; c++) {
            const float4 cp = s_c[c];
            #pragma unroll
            for (int k = 0; k < 8; k++) {
                const float t = fmaf(xs[k], cp.x, fmaf(ys[k], cp.y, fmaf(zs[k], cp.z, cp.w)));
                tmin[k] = fminf(tmin[k], t);
            }
        }
        float local = 0.0f;
        #pragma unroll
        for (int k = 0; k < 8; k++) {
            const float d2 = fmaxf(pn[k] + tmin[k], 0.0f);
            local += smooth_l1(ds[k] - sqrt_fast(d2));
        }

        #pragma unroll
        for (int off = 16; off > 0; off >>= 1)
            local += __shfl_xor_sync(0xFFFFFFFFu, local, off);
        if (lane == 0) wsum[wid] = local;
        __syncthreads();

        if (tid == 0) {
            float v = extra;
            #pragma unroll
            for (int w = 0; w < TPB / 32; w++) v += wsum[w];
            g_part[bid] = v;                                   // plain store
            s_win = (atom_inc_acqrel(&g_count) == NBLK - 1);   // release publishes it
        }
        __syncthreads();

        if (s_win) {
            // parallel final reduce: 256 threads, 1 partial each, double accumulate
            double dv = (double)g_part[tid];
            #pragma unroll
            for (int off = 16; off > 0; off >>= 1)
                dv += __shfl_xor_sync(0xFFFFFFFFu, dv, off);
            if (lane == 0) dsum[wid] = dv;
            __syncthreads();
            if (tid == 0) {
                double tot = 0.0;
                #pragma unroll
                for (int w = 0; w < TPB / 32; w++) tot += dsum[w];
                out[0] = (float)tot;
                g_count = 0;                 // reset for next replay
            }
            if (tid < BB) g_flag[tid] = 0;
        }
    }
}

extern "C" void kernel_launch(void* const* d_in, const int* in_sizes, int n_in,
                              void* d_out, int out_size) {
    const float* disp   = (const float*)d_in[0];       // [B, N]
    const float* sub    = (const float*)d_in[1];       // [B, 3, N]
    const float* cpred  = (const float*)d_in[2];       // [B, 3, C]
    const float* origin = (const float*)d_in[3];       // [B, 9, P]
    const int*   tg     = (const int*)d_in[4];         // [B, P]
    float* out = (float*)d_out;

    k_fused<<<NBLK, TPB>>>(disp, sub, cpred, origin, tg, out);
}